// round 16
// baseline (speedup 1.0000x reference)
#include <cuda_runtime.h>
#include <math.h>

#define Bb 64
#define Cc 8
#define Nn 2048
#define Tt 64
#define NSPLIT 2
#define NROWS (Nn / NSPLIT)                 // 1024 rows per reduce block
#define RED_BLOCKS (Bb * Cc * NSPLIT)       // 1024 (16 per batch, batch-major)
#define AGG_BLOCKS (Bb * 64)                // 4096: 2 chunks per block
#define NT4 (Nn * Tt / 4)                   // 32768 float4 per (b,c)
#define KEEP_FROM 34                        // batches >= this stay L2-resident

// scratch
__device__ float g_part[Bb * Cc * NSPLIT * Tt];   // 256 KB
__device__ float g_att[Bb * Cc * Cc];
__device__ int   g_cnt[Bb];                       // zero-init; reset in tail

union SmemU {
    struct { float alpha[NROWS]; float4 red[256]; } r;            // 8 KB
    struct { float W[64 * 64]; float k[8 * 64]; float m[8 * 64];
             float sc[64]; } t;                                   // ~20.5 KB
};

// ---------------------------------------------------------------------------
// Kernel 1: partial k + last-block-per-batch computes att[b].
// Cache-policy split: early batches evict-first, tail batches evict-normal.
// ---------------------------------------------------------------------------
__global__ void __launch_bounds__(256)
k_reduce_att(const float* __restrict__ x, const float* __restrict__ alpha,
             const float* __restrict__ Wc) {
    __shared__ SmemU S;
    __shared__ int s_last;

    int r     = blockIdx.x;
    int b     = r >> 4;                      // batch-major (16 blocks/batch)
    int sub   = r & 15;
    int c     = sub >> 1;
    int split = sub & 1;
    int bc    = b * Cc + c;
    const float* xp = x + (long)bc * Nn * Tt + (long)split * NROWS * Tt;

    int tid = threadIdx.x;
    for (int i = tid; i < NROWS; i += 256) S.r.alpha[i] = alpha[split * NROWS + i];
    __syncthreads();

    int t4 = tid & 15, row = tid >> 4;
    float4 acc = make_float4(0.f, 0.f, 0.f, 0.f);
    const float4* xv = reinterpret_cast<const float4*>(xp) + t4;

    if (b < KEEP_FROM) {
        // early batches: evict-first — keep them OUT of L2
        #pragma unroll 8
        for (int i = 0; i < NROWS / 16; i++) {   // 64 iters
            int nl = row + i * 16;
            float4 v = __ldcs(&xv[(long)nl * 16]);
            float a = S.r.alpha[nl];
            acc.x += v.x * a; acc.y += v.y * a;
            acc.z += v.z * a; acc.w += v.w * a;
        }
    } else {
        // tail batches: evict-normal — leave resident for k_agg
        #pragma unroll 8
        for (int i = 0; i < NROWS / 16; i++) {
            int nl = row + i * 16;
            float4 v = xv[(long)nl * 16];
            float a = S.r.alpha[nl];
            acc.x += v.x * a; acc.y += v.y * a;
            acc.z += v.z * a; acc.w += v.w * a;
        }
    }

    S.r.red[tid] = acc;
    __syncthreads();
    #pragma unroll
    for (int off = 8; off >= 1; off >>= 1) {
        if (row < off) {
            float4 o = S.r.red[(row + off) * 16 + t4];
            acc.x += o.x; acc.y += o.y; acc.z += o.z; acc.w += o.w;
            S.r.red[tid] = acc;
        }
        __syncthreads();
    }
    if (row == 0)
        reinterpret_cast<float4*>(
            g_part + ((long)bc * NSPLIT + split) * Tt)[t4] = acc;

    // ---- last-block-per-batch tail: compute att[b] ----
    __threadfence();
    if (tid == 0)
        s_last = (atomicAdd(&g_cnt[b], 1) == 16 - 1);
    __syncthreads();
    if (!s_last) return;

    for (int i = tid; i < 64 * 64; i += 256) S.t.W[i] = Wc[i];
    for (int i = tid; i < 8 * 64; i += 256) {
        int cc = i >> 6, t = i & 63;
        const float* gp = g_part + ((long)(b * Cc + cc) * NSPLIT) * Tt + t;
        float s = 0.f;
        #pragma unroll
        for (int p = 0; p < NSPLIT; p++) s += gp[p * Tt];
        S.t.k[i] = s;
    }
    __syncthreads();

    for (int e = tid; e < 512; e += 256) {
        int cc = e >> 6, s = e & 63;
        float a2 = 0.f;
        #pragma unroll
        for (int t = 0; t < 64; t++) a2 += S.t.k[cc * 64 + t] * S.t.W[t * 64 + s];
        S.t.m[e] = a2;
    }
    __syncthreads();

    if (tid < 64) {
        int cc = tid >> 3, d = tid & 7;
        float sc = 0.f;
        #pragma unroll
        for (int s = 0; s < 64; s++) sc += S.t.m[cc * 64 + s] * S.t.k[d * 64 + s];
        S.t.sc[tid] = sc;
    }
    __syncthreads();

    if (tid < 8) {
        float mx = -1e30f;
        #pragma unroll
        for (int j = 0; j < 8; j++) mx = fmaxf(mx, S.t.sc[tid * 8 + j]);
        float e[8], sum = 0.f;
        #pragma unroll
        for (int j = 0; j < 8; j++) { e[j] = __expf(S.t.sc[tid * 8 + j] - mx); sum += e[j]; }
        float inv = 1.f / sum;
        #pragma unroll
        for (int j = 0; j < 8; j++)
            g_att[b * Cc * Cc + tid * Cc + j] = e[j] * inv;
    }
    if (tid == 0) g_cnt[b] = 0;              // reset for next graph replay
}

// ---------------------------------------------------------------------------
// Kernel 2: aggregation, reversed batch order, 2 chunks per block.
// __ldcs x-reads (dead after use); __stcs streaming stores.
// ---------------------------------------------------------------------------
__global__ void __launch_bounds__(256)
k_agg(const float* __restrict__ x, float* __restrict__ out) {
    int b     = (Bb - 1) - (blockIdx.x >> 6);    // reversed batch order
    int cpair = blockIdx.x & 63;                 // chunk pair 0..63
    int tid   = threadIdx.x;

    __shared__ float satt[64];
    if (tid < 64) satt[tid] = g_att[b * 64 + tid];
    __syncthreads();

    const float4* xb = reinterpret_cast<const float4*>(x + (long)b * Cc * Nn * Tt);
    float4*       ob = reinterpret_cast<float4*>(out + (long)b * Cc * Nn * Tt);

    #pragma unroll
    for (int ci = 0; ci < 2; ci++) {
        int p = cpair * 512 + ci * 256 + tid;

        float4 v[8];
        #pragma unroll
        for (int i = 0; i < 8; i++)
            v[i] = __ldcs(&xb[(long)i * NT4 + p]);   // L2 hit then evict (dead)

        #pragma unroll
        for (int c = 0; c < 8; c++) {
            float a0 = satt[c * 8];
            float4 acc;
            acc.x = a0 * v[0].x; acc.y = a0 * v[0].y;
            acc.z = a0 * v[0].z; acc.w = a0 * v[0].w;
            #pragma unroll
            for (int i = 1; i < 8; i++) {
                float a = satt[c * 8 + i];
                acc.x += a * v[i].x; acc.y += a * v[i].y;
                acc.z += a * v[i].z; acc.w += a * v[i].w;
            }
            __stcs(&ob[(long)c * NT4 + p], acc);     // evict-first stream store
        }
    }
}

// ---------------------------------------------------------------------------
extern "C" void kernel_launch(void* const* d_in, const int* in_sizes, int n_in,
                              void* d_out, int out_size) {
    const float* x     = (const float*)d_in[0];
    const float* Wc    = (const float*)d_in[1];
    const float* alpha = (const float*)d_in[2];
    float* out = (float*)d_out;

    k_reduce_att<<<RED_BLOCKS, 256>>>(x, alpha, Wc);
    k_agg<<<AGG_BLOCKS, 256>>>(x, out);
}

// round 17
// speedup vs baseline: 1.0490x; 1.0490x over previous
#include <cuda_runtime.h>
#include <math.h>

#define Bb 64
#define Cc 8
#define Nn 2048
#define Tt 64
#define NSPLIT 4
#define NROWS (Nn / NSPLIT)                 // 512 rows per reduce block
#define RED_BLOCKS (Bb * Cc * NSPLIT)       // 2048 (32 per batch, batch-major)
#define AGG_BLOCKS (Bb * 128)               // 8192
#define NT4 (Nn * Tt / 4)                   // 32768 float4 per (b,c)
#define KEEP_FROM 34                        // batches >= this stay L2-resident

// scratch
__device__ float g_part[Bb * Cc * NSPLIT * Tt];   // 512 KB
__device__ float g_att[Bb * Cc * Cc];
__device__ int   g_cnt[Bb];                       // zero-init; reset in tail

union SmemU {
    struct { float alpha[NROWS]; float4 red[256]; } r;            // 6 KB
    struct { float W[64 * 64]; float k[8 * 64]; float m[8 * 64];
             float sc[64]; } t;                                   // ~20.5 KB
};

// ---------------------------------------------------------------------------
// Kernel 1: partial k + last-block-per-batch computes att[b].
// Cache-policy split: early batches evict-first, tail batches evict-normal
// so L2 at kernel end holds exactly x[KEEP_FROM..63] for k_agg to consume.
// ---------------------------------------------------------------------------
__global__ void __launch_bounds__(256)
k_reduce_att(const float* __restrict__ x, const float* __restrict__ alpha,
             const float* __restrict__ Wc) {
    __shared__ SmemU S;
    __shared__ int s_last;

    int r     = blockIdx.x;
    int b     = r >> 5;                      // batch-major
    int sub   = r & 31;
    int c     = sub >> 2;
    int split = sub & 3;
    int bc    = b * Cc + c;
    const float* xp = x + (long)bc * Nn * Tt + (long)split * NROWS * Tt;

    int tid = threadIdx.x;
    for (int i = tid; i < NROWS; i += 256) S.r.alpha[i] = alpha[split * NROWS + i];
    __syncthreads();

    int t4 = tid & 15, row = tid >> 4;
    float4 acc = make_float4(0.f, 0.f, 0.f, 0.f);
    const float4* xv = reinterpret_cast<const float4*>(xp) + t4;

    if (b < KEEP_FROM) {
        // early batches: evict-first — keep them OUT of L2
        #pragma unroll 8
        for (int i = 0; i < NROWS / 16; i++) {
            int nl = row + i * 16;
            float4 v = __ldcs(&xv[(long)nl * 16]);
            float a = S.r.alpha[nl];
            acc.x += v.x * a; acc.y += v.y * a;
            acc.z += v.z * a; acc.w += v.w * a;
        }
    } else {
        // tail batches: evict-normal — leave resident for k_agg
        #pragma unroll 8
        for (int i = 0; i < NROWS / 16; i++) {
            int nl = row + i * 16;
            float4 v = xv[(long)nl * 16];
            float a = S.r.alpha[nl];
            acc.x += v.x * a; acc.y += v.y * a;
            acc.z += v.z * a; acc.w += v.w * a;
        }
    }

    S.r.red[tid] = acc;
    __syncthreads();
    #pragma unroll
    for (int off = 8; off >= 1; off >>= 1) {
        if (row < off) {
            float4 o = S.r.red[(row + off) * 16 + t4];
            acc.x += o.x; acc.y += o.y; acc.z += o.z; acc.w += o.w;
            S.r.red[tid] = acc;
        }
        __syncthreads();
    }
    if (row == 0)
        reinterpret_cast<float4*>(
            g_part + ((long)bc * NSPLIT + split) * Tt)[t4] = acc;

    // ---- last-block-per-batch tail: compute att[b] ----
    __threadfence();
    if (tid == 0)
        s_last = (atomicAdd(&g_cnt[b], 1) == 32 - 1);
    __syncthreads();
    if (!s_last) return;

    for (int i = tid; i < 64 * 64; i += 256) S.t.W[i] = Wc[i];
    for (int i = tid; i < 8 * 64; i += 256) {
        int cc = i >> 6, t = i & 63;
        const float* gp = g_part + ((long)(b * Cc + cc) * NSPLIT) * Tt + t;
        float s = 0.f;
        #pragma unroll
        for (int p = 0; p < NSPLIT; p++) s += gp[p * Tt];
        S.t.k[i] = s;
    }
    __syncthreads();

    for (int e = tid; e < 512; e += 256) {
        int cc = e >> 6, s = e & 63;
        float a2 = 0.f;
        #pragma unroll
        for (int t = 0; t < 64; t++) a2 += S.t.k[cc * 64 + t] * S.t.W[t * 64 + s];
        S.t.m[e] = a2;
    }
    __syncthreads();

    if (tid < 64) {
        int cc = tid >> 3, d = tid & 7;
        float sc = 0.f;
        #pragma unroll
        for (int s = 0; s < 64; s++) sc += S.t.m[cc * 64 + s] * S.t.k[d * 64 + s];
        S.t.sc[tid] = sc;
    }
    __syncthreads();

    if (tid < 8) {
        float mx = -1e30f;
        #pragma unroll
        for (int j = 0; j < 8; j++) mx = fmaxf(mx, S.t.sc[tid * 8 + j]);
        float e[8], sum = 0.f;
        #pragma unroll
        for (int j = 0; j < 8; j++) { e[j] = __expf(S.t.sc[tid * 8 + j] - mx); sum += e[j]; }
        float inv = 1.f / sum;
        #pragma unroll
        for (int j = 0; j < 8; j++)
            g_att[b * Cc * Cc + tid * Cc + j] = e[j] * inv;
    }
    if (tid == 0) g_cnt[b] = 0;              // reset for next graph replay
}

// ---------------------------------------------------------------------------
// Kernel 2: aggregation, reversed batch order. launch_bounds(256,4) caps regs
// at 64 -> 4 blocks/SM (was 3 at 68 regs).
// ---------------------------------------------------------------------------
__global__ void __launch_bounds__(256, 4)
k_agg(const float* __restrict__ x, float* __restrict__ out) {
    int b     = (Bb - 1) - (blockIdx.x >> 7);    // reversed batch order
    int chunk = blockIdx.x & 127;
    int tid   = threadIdx.x;

    __shared__ float satt[64];
    if (tid < 64) satt[tid] = g_att[b * 64 + tid];
    __syncthreads();

    int p = chunk * 256 + tid;
    const float4* xb = reinterpret_cast<const float4*>(x + (long)b * Cc * Nn * Tt) + p;
    float4*       ob = reinterpret_cast<float4*>(out + (long)b * Cc * Nn * Tt) + p;

    float4 v[8];
    #pragma unroll
    for (int i = 0; i < 8; i++)
        v[i] = __ldcs(xb + (long)i * NT4);       // L2 hit then evict (dead data)

    #pragma unroll
    for (int c = 0; c < 8; c++) {
        float a0 = satt[c * 8];
        float4 acc;
        acc.x = a0 * v[0].x; acc.y = a0 * v[0].y;
        acc.z = a0 * v[0].z; acc.w = a0 * v[0].w;
        #pragma unroll
        for (int i = 1; i < 8; i++) {
            float a = satt[c * 8 + i];
            acc.x += a * v[i].x; acc.y += a * v[i].y;
            acc.z += a * v[i].z; acc.w += a * v[i].w;
        }
        __stcs(ob + (long)c * NT4, acc);         // evict-first streaming store
    }
}

// ---------------------------------------------------------------------------
extern "C" void kernel_launch(void* const* d_in, const int* in_sizes, int n_in,
                              void* d_out, int out_size) {
    const float* x     = (const float*)d_in[0];
    const float* Wc    = (const float*)d_in[1];
    const float* alpha = (const float*)d_in[2];
    float* out = (float*)d_out;

    k_reduce_att<<<RED_BLOCKS, 256>>>(x, alpha, Wc);
    k_agg<<<AGG_BLOCKS, 256>>>(x, out);
}